// round 10
// baseline (speedup 1.0000x reference)
#include <cuda_runtime.h>
#include <stdint.h>

// embeddings: [B=32, L=4, W=512, D=768] f32; segment_ids: [B=32, W=512] i32 sorted/row.
// Out (f32, concat): word [B, D, W] then sent [B, D].
//
// word[b,d,s] = (1/L) * sum_{w: seg[b,w]==s} sum_l emb[b,l,w,d]
// sent[b,d]   = (1/W) * sum_s word[b,d,s]
//
// R9: duty-cycle fix. 8 blocks/SM (smem 26.8KB, launch_bounds reg cap) so
// blocks in different phases overlap their DRAM bursts; serial binary search
// replaced by a parallel boundary scan (unique-writer smem publish).

#define BB 32
#define LL 4
#define WW 512
#define DD 768

#define TILE_S 8           // segments per block
#define CH     8           // subword chunk capacity
#define NTHR   96          // threads per block
#define TILE_D (NTHR * 4)  // 384 d-channels per block (float4/thread)
#define TS_ST  388         // tile_s row stride (floats)

__global__ void zero_sent_kernel(float* __restrict__ sent) {
    int i = blockIdx.x * blockDim.x + threadIdx.x;
    if (i < BB * DD) sent[i] = 0.0f;
}

__global__ __launch_bounds__(NTHR, 8)
void word_agg_kernel(const float* __restrict__ emb,
                     const int*   __restrict__ seg,
                     float*       __restrict__ word,   // [B, D, W]
                     float*       __restrict__ sent)   // [B, D]
{
    __shared__ float tile_w[CH][TILE_D];      //  8 x 384 x 4B = 12,288 B
    __shared__ float tile_s[TILE_S][TS_ST];   //  8 x 388 x 4B = 12,416 B
    __shared__ int   segs[WW];                //  2,048 B
    __shared__ int   sh_lo, sh_hi;

    const int b   = blockIdx.z;
    const int s0  = blockIdx.y * TILE_S;
    const int d0  = blockIdx.x * TILE_D;
    const int tid = threadIdx.x;

    if (tid == 0) { sh_lo = WW; sh_hi = WW; }  // defaults: empty / runs to end

    #pragma unroll
    for (int i = tid; i < WW; i += NTHR) segs[i] = seg[b * WW + i];

    // Zero tile_s (empty segments must output 0).
    {
        float4* t4 = (float4*)&tile_s[0][0];
        const int n4 = TILE_S * (TS_ST / 4);
        const float4 z = make_float4(0.f, 0.f, 0.f, 0.f);
        for (int i = tid; i < n4; i += NTHR) t4[i] = z;
    }
    __syncthreads();

    // Parallel boundary scan: position i is the lower bound of v iff
    // segs[i] >= v and segs[i-1] < v. Unique writer -> plain smem store.
    #pragma unroll
    for (int i = tid; i < WW; i += NTHR) {
        const int v    = segs[i];
        const int prev = (i == 0) ? -1 : segs[i - 1];
        if (v >= s0          && prev < s0)          sh_lo = i;
        if (v >= s0 + TILE_S && prev < s0 + TILE_S) sh_hi = i;
    }
    __syncthreads();

    const int wlo = sh_lo;
    const int whi = sh_hi;

    const int d = d0 + tid * 4;
    const float* __restrict__ base = emb + ((size_t)b * LL * WW) * DD + d;
    const size_t LSTRIDE = (size_t)WW * DD;

    // Run-walk state carried across chunks (a run may straddle a chunk edge).
    int    cur = -1;
    float4 acc = make_float4(0.f, 0.f, 0.f, 0.f);

    for (int w0 = wlo; w0 < whi; w0 += CH) {
        const int nw = min(CH, whi - w0);

        // ---- Phase A: pure streaming into tile_w (by subword position).
        // No loop-carried deps; unroll-2 -> 8 independent LDG.128 in flight.
        #pragma unroll 2
        for (int j = 0; j < nw; ++j) {
            const float* p = base + (size_t)(w0 + j) * DD;
            float4 e0 = *(const float4*)(p);
            float4 e1 = *(const float4*)(p + LSTRIDE);
            float4 e2 = *(const float4*)(p + 2 * LSTRIDE);
            float4 e3 = *(const float4*)(p + 3 * LSTRIDE);
            float4 v;
            v.x = (e0.x + e1.x) + (e2.x + e3.x);
            v.y = (e0.y + e1.y) + (e2.y + e3.y);
            v.z = (e0.z + e1.z) + (e2.z + e3.z);
            v.w = (e0.w + e1.w) + (e2.w + e3.w);
            ((float4*)&tile_w[j][0])[tid] = v;
        }
        __syncthreads();

        // ---- Phase B: smem-only run accumulation (register carry, each
        // tile_s row written exactly once).
        for (int j = 0; j < nw; ++j) {
            const int s = segs[w0 + j];
            if (s != cur) {
                if (cur >= 0) ((float4*)&tile_s[cur - s0][0])[tid] = acc;
                acc = make_float4(0.f, 0.f, 0.f, 0.f);
                cur = s;
            }
            float4 v = ((const float4*)&tile_w[j][0])[tid];
            acc.x += v.x; acc.y += v.y; acc.z += v.z; acc.w += v.w;
        }
        __syncthreads();   // tile_w reusable by next chunk
    }
    if (cur >= 0) ((float4*)&tile_s[cur - s0][0])[tid] = acc;
    __syncthreads();

    // sent contribution: column sum over this s-tile.
    {
        float4 cs = make_float4(0.f, 0.f, 0.f, 0.f);
        #pragma unroll
        for (int s = 0; s < TILE_S; ++s) {
            float4 v = ((const float4*)&tile_s[s][0])[tid];
            cs.x += v.x; cs.y += v.y; cs.z += v.z; cs.w += v.w;
        }
        const float k = 0.25f / (float)WW;
        float* sp = sent + b * DD + d;
        atomicAdd(sp + 0, cs.x * k);
        atomicAdd(sp + 1, cs.y * k);
        atomicAdd(sp + 2, cs.z * k);
        atomicAdd(sp + 3, cs.w * k);
    }

    // Transposed coalesced write: word[b, d0+dd, s0 + ss4*4 .. +3] as float4.
    float* __restrict__ outb = word + ((size_t)b * DD + d0) * WW + s0;
    const int NOUT = (TILE_S / 4) * TILE_D;   // 768 float4 stores
    for (int i2 = tid; i2 < NOUT; i2 += NTHR) {
        const int ss4 = i2 & 1;
        const int dd  = i2 >> 1;
        float4 v;
        v.x = 0.25f * tile_s[ss4 * 4 + 0][dd];
        v.y = 0.25f * tile_s[ss4 * 4 + 1][dd];
        v.z = 0.25f * tile_s[ss4 * 4 + 2][dd];
        v.w = 0.25f * tile_s[ss4 * 4 + 3][dd];
        *(float4*)(outb + (size_t)dd * WW + ss4 * 4) = v;
    }
}

extern "C" void kernel_launch(void* const* d_in, const int* in_sizes, int n_in,
                              void* d_out, int out_size) {
    const float* emb = (const float*)d_in[0];
    const int*   seg = (const int*)d_in[1];

    float* word = (float*)d_out;                   // [B, D, W]
    float* sent = word + (size_t)BB * DD * WW;     // [B, D]

    zero_sent_kernel<<<(BB * DD + 255) / 256, 256>>>(sent);

    dim3 grid(DD / TILE_D, WW / TILE_S, BB);       // (2, 64, 32) = 4096 blocks
    word_agg_kernel<<<grid, NTHR>>>(emb, seg, word, sent);
}

// round 11
// speedup vs baseline: 1.2468x; 1.2468x over previous
#include <cuda_runtime.h>
#include <stdint.h>

// embeddings: [B=32, L=4, W=512, D=768] f32; segment_ids: [B=32, W=512] i32 sorted/row.
// Out (f32, concat): word [B, D, W] then sent [B, D].
//
// word[b,d,s] = (1/L) * sum_{w: seg[b,w]==s} sum_l emb[b,l,w,d]
// sent[b,d]   = (1/W) * sum_s word[b,d,s]
//
// R10: barrier-free main loop. tile_s columns are thread-private (same tid
// writes and reads), so no block syncs until the output transpose. Explicit
// software pipeline: one-pair (8 LDG.128) register lookahead, branch-free
// smem RMW accumulate. Warps free-run -> SM-level DRAM duty cycle no longer
// wave-synchronized by barriers.

#define BB 32
#define LL 4
#define WW 512
#define DD 768

#define TILE_S 16          // segments per block
#define NTHR   96          // threads per block
#define TILE_D (NTHR * 4)  // 384 d-channels per block (float4/thread)
#define TS_ST  388         // tile_s row stride (floats)

__global__ void zero_sent_kernel(float* __restrict__ sent) {
    int i = blockIdx.x * blockDim.x + threadIdx.x;
    if (i < BB * DD) sent[i] = 0.0f;
}

__device__ __forceinline__ float4 sum4(float4 a, float4 b, float4 c, float4 d) {
    float4 r;
    r.x = (a.x + b.x) + (c.x + d.x);
    r.y = (a.y + b.y) + (c.y + d.y);
    r.z = (a.z + b.z) + (c.z + d.z);
    r.w = (a.w + b.w) + (c.w + d.w);
    return r;
}

__global__ __launch_bounds__(NTHR, 6)
void word_agg_kernel(const float* __restrict__ emb,
                     const int*   __restrict__ seg,
                     float*       __restrict__ word,   // [B, D, W]
                     float*       __restrict__ sent)   // [B, D]
{
    __shared__ float tile_s[TILE_S][TS_ST];   // 16 x 388 x 4B = 24,832 B
    __shared__ int   segs[WW];                // 2,048 B

    const int b    = blockIdx.z;
    const int s0   = blockIdx.y * TILE_S;
    const int d0   = blockIdx.x * TILE_D;
    const int tid  = threadIdx.x;
    const int lane = tid & 31;

    #pragma unroll
    for (int i = tid; i < WW; i += NTHR) segs[i] = seg[b * WW + i];

    // Zero tile_s (empty segments must output 0). Thread-owned columns, but
    // zero everything cooperatively before the single barrier.
    {
        float4* t4 = (float4*)&tile_s[0][0];
        const int n4 = TILE_S * (TS_ST / 4);
        const float4 z = make_float4(0.f, 0.f, 0.f, 0.f);
        for (int i = tid; i < n4; i += NTHR) t4[i] = z;
    }
    __syncthreads();   // segs + zeros visible to all

    // Per-warp boundary scan (no block barriers): unique position i with
    // segs[i-1] < bound <= segs[i]; warp-min over candidates.
    int wlo = WW, whi = WW;
    #pragma unroll
    for (int i = lane; i < WW; i += 32) {
        const int v    = segs[i];
        const int prev = (i == 0) ? -1 : segs[i - 1];
        if (prev < s0          && v >= s0)          wlo = i;
        if (prev < s0 + TILE_S && v >= s0 + TILE_S) whi = i;
    }
    wlo = __reduce_min_sync(0xffffffffu, wlo);
    whi = __reduce_min_sync(0xffffffffu, whi);

    const float* __restrict__ base = emb + ((size_t)b * LL * WW) * DD + d0 + tid * 4;
    const size_t LSTRIDE = (size_t)WW * DD;

    // RMW accumulate of a 4-layer sum into the thread-owned tile_s column.
    auto rmw = [&](int widx, float4 v) {
        float4* row = (float4*)&tile_s[segs[widx] - s0][0];
        float4 t = row[tid];
        t.x += v.x; t.y += v.y; t.z += v.z; t.w += v.w;
        row[tid] = t;
    };

    int w = wlo;
    if (w + 1 < whi) {
        // Pipeline prologue: load pair (w, w+1) — 8 independent LDG.128.
        const float* p0 = base + (size_t)w * DD;
        const float* p1 = p0 + DD;
        float4 c0 = *(const float4*)(p0);
        float4 c1 = *(const float4*)(p0 + LSTRIDE);
        float4 c2 = *(const float4*)(p0 + 2 * LSTRIDE);
        float4 c3 = *(const float4*)(p0 + 3 * LSTRIDE);
        float4 c4 = *(const float4*)(p1);
        float4 c5 = *(const float4*)(p1 + LSTRIDE);
        float4 c6 = *(const float4*)(p1 + 2 * LSTRIDE);
        float4 c7 = *(const float4*)(p1 + 3 * LSTRIDE);

        for (; w + 3 < whi; w += 2) {
            // Issue next pair's 8 loads BEFORE consuming current pair.
            const float* q0 = base + (size_t)(w + 2) * DD;
            const float* q1 = q0 + DD;
            float4 n0 = *(const float4*)(q0);
            float4 n1 = *(const float4*)(q0 + LSTRIDE);
            float4 n2 = *(const float4*)(q0 + 2 * LSTRIDE);
            float4 n3 = *(const float4*)(q0 + 3 * LSTRIDE);
            float4 n4 = *(const float4*)(q1);
            float4 n5 = *(const float4*)(q1 + LSTRIDE);
            float4 n6 = *(const float4*)(q1 + 2 * LSTRIDE);
            float4 n7 = *(const float4*)(q1 + 3 * LSTRIDE);

            rmw(w,     sum4(c0, c1, c2, c3));
            rmw(w + 1, sum4(c4, c5, c6, c7));

            c0 = n0; c1 = n1; c2 = n2; c3 = n3;
            c4 = n4; c5 = n5; c6 = n6; c7 = n7;
        }
        // Drain the last preloaded pair.
        rmw(w,     sum4(c0, c1, c2, c3));
        rmw(w + 1, sum4(c4, c5, c6, c7));
        w += 2;
    }
    // 0 or 1 leftover subword.
    for (; w < whi; ++w) {
        const float* p = base + (size_t)w * DD;
        float4 e0 = *(const float4*)(p);
        float4 e1 = *(const float4*)(p + LSTRIDE);
        float4 e2 = *(const float4*)(p + 2 * LSTRIDE);
        float4 e3 = *(const float4*)(p + 3 * LSTRIDE);
        rmw(w, sum4(e0, e1, e2, e3));
    }

    // sent contribution (thread-owned columns, still no barrier needed).
    {
        float4 cs = make_float4(0.f, 0.f, 0.f, 0.f);
        #pragma unroll
        for (int s = 0; s < TILE_S; ++s) {
            float4 v = ((const float4*)&tile_s[s][0])[tid];
            cs.x += v.x; cs.y += v.y; cs.z += v.z; cs.w += v.w;
        }
        const float k = 0.25f / (float)WW;
        float* sp = sent + b * DD + d0 + tid * 4;
        atomicAdd(sp + 0, cs.x * k);
        atomicAdd(sp + 1, cs.y * k);
        atomicAdd(sp + 2, cs.z * k);
        atomicAdd(sp + 3, cs.w * k);
    }

    __syncthreads();   // the ONE cross-thread handoff: transpose read below

    // Transposed coalesced write: word[b, d0+dd, s0 + ss4*4 .. +3] as float4.
    float* __restrict__ outb = word + ((size_t)b * DD + d0) * WW + s0;
    const int NOUT = (TILE_S / 4) * TILE_D;   // 1536 float4 stores
    for (int i2 = tid; i2 < NOUT; i2 += NTHR) {
        const int ss4 = i2 & 3;
        const int dd  = i2 >> 2;
        float4 v;
        v.x = 0.25f * tile_s[ss4 * 4 + 0][dd];
        v.y = 0.25f * tile_s[ss4 * 4 + 1][dd];
        v.z = 0.25f * tile_s[ss4 * 4 + 2][dd];
        v.w = 0.25f * tile_s[ss4 * 4 + 3][dd];
        *(float4*)(outb + (size_t)dd * WW + ss4 * 4) = v;
    }
}

extern "C" void kernel_launch(void* const* d_in, const int* in_sizes, int n_in,
                              void* d_out, int out_size) {
    const float* emb = (const float*)d_in[0];
    const int*   seg = (const int*)d_in[1];

    float* word = (float*)d_out;                   // [B, D, W]
    float* sent = word + (size_t)BB * DD * WW;     // [B, D]

    zero_sent_kernel<<<(BB * DD + 255) / 256, 256>>>(sent);

    dim3 grid(DD / TILE_D, WW / TILE_S, BB);       // (2, 32, 32) = 2048 blocks
    word_agg_kernel<<<grid, NTHR>>>(emb, seg, word, sent);
}